// round 16
// baseline (speedup 1.0000x reference)
#include <cuda_runtime.h>
#include <math.h>
#include <stdint.h>

#define BB   32
#define NN   1024
#define DD   64
#define HH   128
#define OUTD 8
#define KK   16
#define CAP  128
#define NODES (BB*NN)

// ---------------- scratch (static device globals; no runtime alloc) ----------
__device__ float    g_maskf[NODES];
__device__ float    g_px[NODES];
__device__ float    g_py[NODES];
__device__ float    g_dinv[NODES];
__device__ float    g_coef[NODES];
__device__ int      g_cnt[NODES];
__device__ unsigned g_mask[NODES*32];
__device__ int      g_rev[NODES*CAP];
__device__ float    g_a[NODES*HH];           // pregather output (GEMM input)
__device__ float    g_h[NODES*HH];           // layer activations
__device__ float    g_w1hi[DD*HH], g_w1lo[DD*HH];    // tf32-split W1
__device__ float    g_w2hi[HH*HH], g_w2lo[HH*HH];    // tf32-split W2

// tf32 helpers (legacy mma path; supported on base sm_100 target)
__device__ __forceinline__ unsigned f2tf(float x) {
    unsigned r;
    asm("cvt.rna.tf32.f32 %0, %1;" : "=r"(r) : "f"(x));
    return r;
}
#define MMA_TF32(d0,d1,d2,d3, a0,a1,a2,a3, b0,b1) \
    asm volatile("mma.sync.aligned.m16n8k8.row.col.f32.tf32.tf32.f32 " \
        "{%0,%1,%2,%3}, {%4,%5,%6,%7}, {%8,%9}, {%10,%11,%12,%13};" \
        : "=f"(d0), "=f"(d1), "=f"(d2), "=f"(d3) \
        : "r"(a0), "r"(a1), "r"(a2), "r"(a3), "r"(b0), "r"(b1), \
          "f"(d0), "f"(d1), "f"(d2), "f"(d3))

// ---------------- 0. weight split: W -> tf32 hi/lo (row-major copy) -----------
template<int K>
__global__ void convert_w_kernel(const float* __restrict__ W) {
    float* hi = (K == DD) ? g_w1hi : g_w2hi;
    float* lo = (K == DD) ? g_w1lo : g_w2lo;
    int idx = blockIdx.x * 256 + threadIdx.x;        // < K*128
    float v = W[idx];
    unsigned h = f2tf(v);
    float hf = __uint_as_float(h);
    unsigned l = f2tf(v - hf);
    hi[idx] = hf;
    lo[idx] = __uint_as_float(l);
}

// ---------------- 1. mask / pos init + zero bitmask ---------------------------
__global__ void prep_kernel(const float* __restrict__ obs) {
    int m = blockIdx.x * 256 + threadIdx.x;
    const float4* row = (const float4*)(obs + m * DD);
    bool any = false;
    float x0 = 0.f, y0 = 0.f;
    #pragma unroll
    for (int i = 0; i < 16; i++) {
        float4 v = row[i];
        if (i == 0) { x0 = v.x; y0 = v.y; }
        any = any || (v.x != 0.f) || (v.y != 0.f) || (v.z != 0.f) || (v.w != 0.f);
    }
    float mf = any ? 1.f : 0.f;
    g_maskf[m] = mf;
    g_px[m] = x0;
    g_py[m] = y0;
    int4 z = {0,0,0,0};
    int4* mk = (int4*)&g_mask[m * 32];
    #pragma unroll
    for (int i = 0; i < 8; i++) mk[i] = z;
}

// ---------------- 2. kNN top-(K+1) + fused edge scatter (R14-proven) ----------
#define REGRP(G, DM, DS) do {                                    \
    unsigned bm = 0xFFFFFFFFu; int bs = 0;                       \
    _Pragma("unroll")                                            \
    for (int s = (G)*8; s < (G)*8 + 8; s++) {                    \
        bool ok = (((sel >> s) & 1u) == 0u) && (u[s] < bm);      \
        bm = ok ? u[s] : bm;                                     \
        bs = ok ? s    : bs;                                     \
    }                                                            \
    DM = bm; DS = bs;                                            \
} while (0)
#define REGRP0(G, DM, DS) do {                                   \
    unsigned bm = 0xFFFFFFFFu; int bs = 0;                       \
    _Pragma("unroll")                                            \
    for (int s = (G)*8; s < (G)*8 + 8; s++) {                    \
        bool ok = (u[s] < bm);                                   \
        bm = ok ? u[s] : bm;                                     \
        bs = ok ? s    : bs;                                     \
    }                                                            \
    DM = bm; DS = bs;                                            \
} while (0)

__global__ __launch_bounds__(256) void topk_kernel() {
    __shared__ float sx[NN], sy[NN];
    int b = blockIdx.y;
    for (int j = threadIdx.x; j < NN; j += 256) {
        float mf = g_maskf[b*NN + j];
        float X = g_px[b*NN + j], Y = g_py[b*NN + j];
        float inf = __int_as_float(0x7F800000);
        sx[j] = (mf != 0.f) ? X : inf;
        sy[j] = (mf != 0.f) ? Y : inf;
    }
    __syncthreads();

    int warp = threadIdx.x >> 5, lane = threadIdx.x & 31;
    int n = blockIdx.x * 8 + warp;
    float xn = sx[n], yn = sy[n];
    bool src_valid = (g_maskf[b*NN + n] != 0.f);

    unsigned u[32];
    #pragma unroll
    for (int i = 0; i < 32; i++) {
        int j = (i << 5) | lane;
        float dx = xn - sx[j];
        float dy = yn - sy[j];
        float d2 = __fadd_rn(__fmul_rn(dx, dx), __fmul_rn(dy, dy));
        u[i] = __float_as_uint(d2);
    }

    unsigned sel = 0;
    unsigned gm0, gm1, gm2, gm3;
    int      gs0, gs1, gs2, gs3;
    REGRP0(0, gm0, gs0);
    REGRP0(1, gm1, gs1);
    REGRP0(2, gm2, gs2);
    REGRP0(3, gm3, gs3);
    unsigned lmin = gm0; int lslot = gs0;
    if (gm1 < lmin) { lmin = gm1; lslot = gs1; }
    if (gm2 < lmin) { lmin = gm2; lslot = gs2; }
    if (gm3 < lmin) { lmin = gm3; lslot = gs3; }

    int mword = (b*NN) * 32 + ((n >> 5));
    unsigned mbit = 1u << (n & 31);

    #pragma unroll 1
    for (int r = 0; r < KK + 1; r++) {
        unsigned w = __reduce_min_sync(0xffffffffu, lmin);
        int cand = (lmin == w) ? ((lslot << 5) | lane) : 0x7FFFFFFF;
        int jwin = __reduce_min_sync(0xffffffffu, cand);
        if (r > 0 && src_valid && lane == 0)
            atomicOr(&g_mask[mword + jwin * 32], mbit);
        if (r < KK && lane == (jwin & 31)) {
            int slot = jwin >> 5;
            sel |= (1u << slot);
            int g = slot >> 3;
            unsigned gm; int gs;
            if      (g == 0) { REGRP(0, gm, gs); gm0 = gm; gs0 = gs; }
            else if (g == 1) { REGRP(1, gm, gs); gm1 = gm; gs1 = gs; }
            else if (g == 2) { REGRP(2, gm, gs); gm2 = gm; gs2 = gs; }
            else             { REGRP(3, gm, gs); gm3 = gm; gs3 = gs; }
            lmin = gm0; lslot = gs0;
            if (gm1 < lmin) { lmin = gm1; lslot = gs1; }
            if (gm2 < lmin) { lmin = gm2; lslot = gs2; }
            if (gm3 < lmin) { lmin = gm3; lslot = gs3; }
        }
    }
}

// ---------------- 3. listify: bitmask -> sorted list + deg/dinv/coef ----------
__global__ void listify_kernel() {
    int lane = threadIdx.x & 31;
    int m = (blockIdx.x * 256 + threadIdx.x) >> 5;
    unsigned wbits = g_mask[m * 32 + lane];
    int c = __popc(wbits);
    int pre = c;
    #pragma unroll
    for (int s = 1; s < 32; s <<= 1) {
        int nv = __shfl_up_sync(0xffffffffu, pre, s);
        if (lane >= s) pre += nv;
    }
    int total = __shfl_sync(0xffffffffu, pre, 31);
    int base  = pre - c;
    if (lane == 0) {
        float mf = g_maskf[m];
        float d  = (float)total + 2.f * mf;
        float di = d > 0.f ? (1.0f / sqrtf(d)) : 0.f;
        g_dinv[m] = di;
        g_coef[m] = di * mf;
        g_cnt[m]  = total < CAP ? total : CAP;
    }
    int gb = (m & ~(NN - 1)) + (lane << 5);
    while (wbits) {
        int j = __ffs(wbits) - 1;
        wbits &= wbits - 1;
        if (base < CAP) g_rev[m * CAP + base] = gb + j;
        base++;
    }
}

// ---------------- 4. pregather, float4 channels (R14-proven) -------------------
template<int DIN, bool FROMOBS>
__global__ void pregather_kernel(const float* __restrict__ obs) {
    const float4* X = FROMOBS ? (const float4*)obs : (const float4*)g_h;
    constexpr int C4  = DIN / 4;
    constexpr int NPB = 128 / C4;
    int local = threadIdx.x / C4;
    int c     = threadIdx.x % C4;
    int m = blockIdx.x * NPB + local;
    __shared__ int   ssrc[NPB][CAP];
    __shared__ float scf[NPB][CAP];
    int nsrc = g_cnt[m];
    for (int s = c; s < nsrc; s += C4) {
        int src = g_rev[m * CAP + s];
        ssrc[local][s] = src * C4;
        scf[local][s]  = g_coef[src];
    }
    __syncthreads();
    float4 agg  = {0.f, 0.f, 0.f, 0.f};
    float4 agg2 = {0.f, 0.f, 0.f, 0.f};
    int s = 0;
    for (; s + 1 < nsrc; s += 2) {
        float  cf0 = scf[local][s],     cf1 = scf[local][s + 1];
        float4 v0  = X[ssrc[local][s]     + c];
        float4 v1  = X[ssrc[local][s + 1] + c];
        agg.x  = fmaf(cf0, v0.x, agg.x);  agg.y  = fmaf(cf0, v0.y, agg.y);
        agg.z  = fmaf(cf0, v0.z, agg.z);  agg.w  = fmaf(cf0, v0.w, agg.w);
        agg2.x = fmaf(cf1, v1.x, agg2.x); agg2.y = fmaf(cf1, v1.y, agg2.y);
        agg2.z = fmaf(cf1, v1.z, agg2.z); agg2.w = fmaf(cf1, v1.w, agg2.w);
    }
    if (s < nsrc) {
        float  cf = scf[local][s];
        float4 v  = X[ssrc[local][s] + c];
        agg.x = fmaf(cf, v.x, agg.x); agg.y = fmaf(cf, v.y, agg.y);
        agg.z = fmaf(cf, v.z, agg.z); agg.w = fmaf(cf, v.w, agg.w);
    }
    agg.x += agg2.x; agg.y += agg2.y; agg.z += agg2.z; agg.w += agg2.w;
    float  dm  = g_dinv[m];
    float  dm2 = 2.f * dm * dm;
    float4 xm  = X[m * C4 + c];
    float4 o;
    o.x = dm * agg.x + dm2 * xm.x;
    o.y = dm * agg.y + dm2 * xm.y;
    o.z = dm * agg.z + dm2 * xm.z;
    o.w = dm * agg.w + dm2 * xm.w;
    ((float4*)g_a)[m * C4 + c] = o;
}

// ---------------- 5. tf32-split mma GEMM + bias + tanh (+ fused head) ---------
// Tile 64 rows x 128 cols, 8 warps: warp w -> rows (w>>1)*16..+15, cols (w&1)*64..+63.
// D = Xhi@Whi + Xlo@Whi + Xhi@Wlo via m16n8k8 tf32 mma; fp32 accumulate.
// SMEM (floats): XS [32][72] @0 | WHI [32][136] @2304 | WLO @6656 | BIAS @11008.
// FINAL: HS [64][128] aliases @2304 after mainloop.
#define XS(k,r)  smem_f[(k)*72 + (r)]
#define WHI(k,c) smem_f[2304 + (k)*136 + (c)]
#define WLO(k,c) smem_f[6656 + (k)*136 + (c)]
#define HS(r,c)  smem_f[2304 + (r)*128 + (c)]

template<int DIN, bool FINAL>
__global__ __launch_bounds__(256) void gemm_kernel(const float* __restrict__ bias,
                                                   const float* __restrict__ Wout,
                                                   const float* __restrict__ bout,
                                                   float* __restrict__ out) {
    const float* X   = (const float*)g_a;
    const float* Whi = (DIN == DD) ? (const float*)g_w1hi : (const float*)g_w2hi;
    const float* Wlo = (DIN == DD) ? (const float*)g_w1lo : (const float*)g_w2lo;
    __shared__ __align__(16) float smem_f[11136];
    int tid  = threadIdx.x;
    int lane = tid & 31;
    int warp = tid >> 5;
    int row0 = blockIdx.x * 64;
    int mr   = (warp >> 1) * 16;          // warp row base within tile
    int nc   = (warp & 1) * 64;           // warp col base within tile
    int tg   = lane >> 2;                 // fragment group id (0..7)
    int tk   = lane & 3;                  // thread-in-group (0..3)

    if (tid < 128) smem_f[11008 + tid] = bias[tid];

    float acc[8][4];
    #pragma unroll
    for (int t = 0; t < 8; t++)
        #pragma unroll
        for (int q = 0; q < 4; q++) acc[t][q] = 0.f;

    for (int kc = 0; kc < DIN; kc += 32) {
        #pragma unroll
        for (int t = 0; t < 2; t++) {                 // X tile 64x32, transposed
            int f = tid + t * 256;
            int r = f >> 3;
            int kq = (f & 7) << 2;
            float4 v = *(const float4*)(X + (row0 + r) * DIN + kc + kq);
            XS(kq+0, r) = v.x; XS(kq+1, r) = v.y;
            XS(kq+2, r) = v.z; XS(kq+3, r) = v.w;
        }
        #pragma unroll
        for (int t = 0; t < 4; t++) {                 // W hi+lo tile 32x128
            int f = tid + t * 256;
            int k = f >> 5;
            int c = (f & 31) << 2;
            float4 vh = *(const float4*)(Whi + (kc + k) * HH + c);
            WHI(k, c+0) = vh.x; WHI(k, c+1) = vh.y; WHI(k, c+2) = vh.z; WHI(k, c+3) = vh.w;
            float4 vl = *(const float4*)(Wlo + (kc + k) * HH + c);
            WLO(k, c+0) = vl.x; WLO(k, c+1) = vl.y; WLO(k, c+2) = vl.z; WLO(k, c+3) = vl.w;
        }
        __syncthreads();
        #pragma unroll
        for (int ks = 0; ks < 4; ks++) {
            int k0 = ks * 8;
            // A fragments (m16 x k8), split hi/lo
            float x0 = XS(k0 + tk,     mr + tg);
            float x1 = XS(k0 + tk,     mr + tg + 8);
            float x2 = XS(k0 + tk + 4, mr + tg);
            float x3 = XS(k0 + tk + 4, mr + tg + 8);
            unsigned ah0 = f2tf(x0), ah1 = f2tf(x1), ah2 = f2tf(x2), ah3 = f2tf(x3);
            unsigned al0 = f2tf(x0 - __uint_as_float(ah0));
            unsigned al1 = f2tf(x1 - __uint_as_float(ah1));
            unsigned al2 = f2tf(x2 - __uint_as_float(ah2));
            unsigned al3 = f2tf(x3 - __uint_as_float(ah3));
            #pragma unroll
            for (int nt = 0; nt < 8; nt++) {
                int col = nc + nt * 8 + tg;
                unsigned bh0 = __float_as_uint(WHI(k0 + tk,     col));
                unsigned bh1 = __float_as_uint(WHI(k0 + tk + 4, col));
                unsigned bl0 = __float_as_uint(WLO(k0 + tk,     col));
                unsigned bl1 = __float_as_uint(WLO(k0 + tk + 4, col));
                MMA_TF32(acc[nt][0], acc[nt][1], acc[nt][2], acc[nt][3],
                         ah0, ah1, ah2, ah3, bh0, bh1);
                MMA_TF32(acc[nt][0], acc[nt][1], acc[nt][2], acc[nt][3],
                         al0, al1, al2, al3, bh0, bh1);
                MMA_TF32(acc[nt][0], acc[nt][1], acc[nt][2], acc[nt][3],
                         ah0, ah1, ah2, ah3, bl0, bl1);
            }
        }
        __syncthreads();
    }

    const float* sbias = &smem_f[11008];
    if (!FINAL) {
        #pragma unroll
        for (int nt = 0; nt < 8; nt++) {
            int c = nc + nt * 8 + tk * 2;
            int r0 = row0 + mr + tg;
            float2 v0, v1;
            v0.x = tanhf(acc[nt][0] + sbias[c]);
            v0.y = tanhf(acc[nt][1] + sbias[c + 1]);
            v1.x = tanhf(acc[nt][2] + sbias[c]);
            v1.y = tanhf(acc[nt][3] + sbias[c + 1]);
            *(float2*)(g_h + (size_t)r0 * HH + c)       = v0;
            *(float2*)(g_h + (size_t)(r0 + 8) * HH + c) = v1;
        }
    } else {
        #pragma unroll
        for (int nt = 0; nt < 8; nt++) {
            int c = nc + nt * 8 + tk * 2;
            int r = mr + tg;
            HS(r,     c)     = tanhf(acc[nt][0] + sbias[c]);
            HS(r,     c + 1) = tanhf(acc[nt][1] + sbias[c + 1]);
            HS(r + 8, c)     = tanhf(acc[nt][2] + sbias[c]);
            HS(r + 8, c + 1) = tanhf(acc[nt][3] + sbias[c + 1]);
        }
        __syncthreads();
        float wreg[32];                               // Wout rows lane*4..+3
        #pragma unroll
        for (int i = 0; i < 8; i++)
            *(float4*)&wreg[i*4] = *(const float4*)(Wout + lane * 32 + i * 4);
        #pragma unroll
        for (int rr = 0; rr < 8; rr++) {
            int row = warp * 8 + rr;
            float4 hv = *(const float4*)&HS(row, lane*4);
            float hk[4] = {hv.x, hv.y, hv.z, hv.w};
            float a2[8];
            #pragma unroll
            for (int o = 0; o < 8; o++) a2[o] = 0.f;
            #pragma unroll
            for (int j = 0; j < 4; j++)
                #pragma unroll
                for (int o = 0; o < 8; o++)
                    a2[o] = fmaf(hk[j], wreg[j*8 + o], a2[o]);
            #pragma unroll
            for (int o = 0; o < 8; o++)
                #pragma unroll
                for (int s = 16; s >= 1; s >>= 1)
                    a2[o] += __shfl_xor_sync(0xffffffffu, a2[o], s);
            if (lane == 0) {
                int m = row0 + row;
                float mf = g_maskf[m];
                #pragma unroll
                for (int o = 0; o < 8; o++)
                    out[m * OUTD + o] = (a2[o] + bout[o]) * mf;
            }
        }
    }
}

// ---------------- launch ------------------------------------------------------
extern "C" void kernel_launch(void* const* d_in, const int* in_sizes, int n_in,
                              void* d_out, int out_size) {
    const float* obs  = (const float*)d_in[0];
    const float* W1   = (const float*)d_in[1];
    const float* b1   = (const float*)d_in[2];
    const float* W2   = (const float*)d_in[3];
    const float* b2   = (const float*)d_in[4];
    const float* Wout = (const float*)d_in[5];
    const float* bout = (const float*)d_in[6];
    float* out = (float*)d_out;

    convert_w_kernel<DD><<<(DD*HH)/256, 256>>>(W1);
    convert_w_kernel<HH><<<(HH*HH)/256, 256>>>(W2);
    prep_kernel   <<<NODES/256, 256>>>(obs);
    topk_kernel   <<<dim3(NN/8, BB), 256>>>();
    listify_kernel<<<NODES/8, 256>>>();

    pregather_kernel<DD, true> <<<NODES/8, 128>>>(obs);
    gemm_kernel<DD, false><<<NODES/64, 256>>>(b1, 0, 0, 0);
    pregather_kernel<HH, false><<<NODES/4, 128>>>(obs);
    gemm_kernel<HH, true><<<NODES/64, 256>>>(b2, Wout, bout, out);
}

// round 17
// speedup vs baseline: 1.2379x; 1.2379x over previous
#include <cuda_runtime.h>
#include <math.h>
#include <stdint.h>

#define BB   32
#define NN   1024
#define DD   64
#define HH   128
#define OUTD 8
#define KK   16
#define CAP  128
#define NODES (BB*NN)

// ---------------- scratch (static device globals; no runtime alloc) ----------
__device__ float    g_maskf[NODES];
__device__ float    g_px[NODES];
__device__ float    g_py[NODES];
__device__ float    g_dinv[NODES];
__device__ float    g_coef[NODES];
__device__ int      g_cnt[NODES];
__device__ unsigned g_mask[NODES*32];
__device__ int      g_rev[NODES*CAP];
__device__ float    g_a[NODES*HH];           // pregather output (GEMM input)
__device__ float    g_h[NODES*HH];           // layer activations

// ---------------- 1. mask / pos init + zero bitmask ---------------------------
__global__ void prep_kernel(const float* __restrict__ obs) {
    int m = blockIdx.x * 256 + threadIdx.x;
    const float4* row = (const float4*)(obs + m * DD);
    bool any = false;
    float x0 = 0.f, y0 = 0.f;
    #pragma unroll
    for (int i = 0; i < 16; i++) {
        float4 v = row[i];
        if (i == 0) { x0 = v.x; y0 = v.y; }
        any = any || (v.x != 0.f) || (v.y != 0.f) || (v.z != 0.f) || (v.w != 0.f);
    }
    float mf = any ? 1.f : 0.f;
    g_maskf[m] = mf;
    g_px[m] = x0;
    g_py[m] = y0;
    int4 z = {0,0,0,0};
    int4* mk = (int4*)&g_mask[m * 32];
    #pragma unroll
    for (int i = 0; i < 8; i++) mk[i] = z;
}

// ---------------- 2. kNN top-(K+1) + fused edge scatter ------------------------
// Keys (fp32 d2 bits; bit order == numeric order for non-negatives) live in
// padded SMEM: pad(j) = j + j/32 -> bank (i + j%32)%32, conflict-free for both
// build (fixed i, lane varies) and refill (fixed domain L, lane=i varies).
// Lane L owns domain {j : j%32 == L}, holding only (min, argmin j) in regs.
// Winner per round: REDUX min of d2 bits, then REDUX min j among tied
// (== lax.top_k tie semantics exactly). Pop = STS sentinel; refill of the
// owner's domain is WARP-PARALLEL: 1 LDS/lane + REDUX + ballot + ffs (min i
// => min j, exact). No sel bitmask, no divergent 8-slot rescans.
__global__ __launch_bounds__(256) void topk_kernel() {
    __shared__ float sx[NN], sy[NN];
    __shared__ unsigned skey[8][1056];               // 33 * 32 per node
    int b = blockIdx.y;
    for (int j = threadIdx.x; j < NN; j += 256) {
        float mf = g_maskf[b*NN + j];
        float X = g_px[b*NN + j], Y = g_py[b*NN + j];
        float inf = __int_as_float(0x7F800000);
        sx[j] = (mf != 0.f) ? X : inf;
        sy[j] = (mf != 0.f) ? Y : inf;
    }
    __syncthreads();

    int warp = threadIdx.x >> 5, lane = threadIdx.x & 31;
    int n = blockIdx.x * 8 + warp;
    float xn = sx[n], yn = sy[n];
    bool src_valid = (g_maskf[b*NN + n] != 0.f);
    unsigned* K = skey[warp];

    // build: lane computes its own domain j = (i<<5)|lane, tracks running min
    unsigned lmin = 0xFFFFFFFFu; int lj = 0;
    #pragma unroll
    for (int i = 0; i < 32; i++) {
        int j = (i << 5) | lane;
        float dx = xn - sx[j];
        float dy = yn - sy[j];
        float d2 = __fadd_rn(__fmul_rn(dx, dx), __fmul_rn(dy, dy));
        unsigned k = __float_as_uint(d2);
        K[i * 33 + lane] = k;
        if (k < lmin) { lmin = k; lj = j; }          // strict < => lowest j on ties
    }
    __syncwarp();

    int mword = (b*NN) * 32 + (n >> 5);
    unsigned mbit = 1u << (n & 31);

    #pragma unroll 1
    for (int r = 0; r < KK + 1; r++) {
        // winner: min d2 bits, then min j among tied lanes
        unsigned w = __reduce_min_sync(0xffffffffu, lmin);
        int cand = (lmin == w) ? lj : 0x7FFFFFFF;
        int jwin = __reduce_min_sync(0xffffffffu, cand);
        // fused scatter: mark source n in target jwin's bitmask
        if (r > 0 && src_valid && lane == 0)
            atomicOr(&g_mask[mword + jwin * 32], mbit);
        if (r < KK) {
            int L = jwin & 31;                       // domain to refill
            if (lane == 0) K[jwin + (jwin >> 5)] = 0xFFFFFFFFu;   // pop
            __syncwarp();
            unsigned k2 = K[lane * 33 + L];          // warp-parallel domain scan
            unsigned w2 = __reduce_min_sync(0xffffffffu, k2);
            unsigned tied = __ballot_sync(0xffffffffu, k2 == w2);
            int j2 = ((__ffs(tied) - 1) << 5) | L;   // min i => min j in domain
            if (lane == L) { lmin = w2; lj = j2; }
            __syncwarp();
        }
    }
}

// ---------------- 3. listify: bitmask -> sorted list + deg/dinv/coef ----------
__global__ void listify_kernel() {
    int lane = threadIdx.x & 31;
    int m = (blockIdx.x * 256 + threadIdx.x) >> 5;
    unsigned wbits = g_mask[m * 32 + lane];
    int c = __popc(wbits);
    int pre = c;
    #pragma unroll
    for (int s = 1; s < 32; s <<= 1) {
        int nv = __shfl_up_sync(0xffffffffu, pre, s);
        if (lane >= s) pre += nv;
    }
    int total = __shfl_sync(0xffffffffu, pre, 31);
    int base  = pre - c;
    if (lane == 0) {
        float mf = g_maskf[m];
        float d  = (float)total + 2.f * mf;
        float di = d > 0.f ? (1.0f / sqrtf(d)) : 0.f;
        g_dinv[m] = di;
        g_coef[m] = di * mf;
        g_cnt[m]  = total < CAP ? total : CAP;
    }
    int gb = (m & ~(NN - 1)) + (lane << 5);
    while (wbits) {
        int j = __ffs(wbits) - 1;
        wbits &= wbits - 1;
        if (base < CAP) g_rev[m * CAP + base] = gb + j;
        base++;
    }
}

// ---------------- 4. pregather, float4 channels (R14-proven) -------------------
template<int DIN, bool FROMOBS>
__global__ void pregather_kernel(const float* __restrict__ obs) {
    const float4* X = FROMOBS ? (const float4*)obs : (const float4*)g_h;
    constexpr int C4  = DIN / 4;
    constexpr int NPB = 128 / C4;
    int local = threadIdx.x / C4;
    int c     = threadIdx.x % C4;
    int m = blockIdx.x * NPB + local;
    __shared__ int   ssrc[NPB][CAP];
    __shared__ float scf[NPB][CAP];
    int nsrc = g_cnt[m];
    for (int s = c; s < nsrc; s += C4) {
        int src = g_rev[m * CAP + s];
        ssrc[local][s] = src * C4;
        scf[local][s]  = g_coef[src];
    }
    __syncthreads();
    float4 agg  = {0.f, 0.f, 0.f, 0.f};
    float4 agg2 = {0.f, 0.f, 0.f, 0.f};
    int s = 0;
    for (; s + 1 < nsrc; s += 2) {
        float  cf0 = scf[local][s],     cf1 = scf[local][s + 1];
        float4 v0  = X[ssrc[local][s]     + c];
        float4 v1  = X[ssrc[local][s + 1] + c];
        agg.x  = fmaf(cf0, v0.x, agg.x);  agg.y  = fmaf(cf0, v0.y, agg.y);
        agg.z  = fmaf(cf0, v0.z, agg.z);  agg.w  = fmaf(cf0, v0.w, agg.w);
        agg2.x = fmaf(cf1, v1.x, agg2.x); agg2.y = fmaf(cf1, v1.y, agg2.y);
        agg2.z = fmaf(cf1, v1.z, agg2.z); agg2.w = fmaf(cf1, v1.w, agg2.w);
    }
    if (s < nsrc) {
        float  cf = scf[local][s];
        float4 v  = X[ssrc[local][s] + c];
        agg.x = fmaf(cf, v.x, agg.x); agg.y = fmaf(cf, v.y, agg.y);
        agg.z = fmaf(cf, v.z, agg.z); agg.w = fmaf(cf, v.w, agg.w);
    }
    agg.x += agg2.x; agg.y += agg2.y; agg.z += agg2.z; agg.w += agg2.w;
    float  dm  = g_dinv[m];
    float  dm2 = 2.f * dm * dm;
    float4 xm  = X[m * C4 + c];
    float4 o;
    o.x = dm * agg.x + dm2 * xm.x;
    o.y = dm * agg.y + dm2 * xm.y;
    o.z = dm * agg.z + dm2 * xm.z;
    o.w = dm * agg.w + dm2 * xm.w;
    ((float4*)g_a)[m * C4 + c] = o;
}

// ---------------- 5. GEMM + bias + tanh (+ optional fused output head) --------
#define XS(k,r) smem_f[(k)*64 + (r)]
#define WS(k,c) smem_f[2048 + (k)*128 + (c)]
#define HS(r,c) smem_f[(r)*128 + (c)]

template<int DIN, bool FINAL>
__global__ __launch_bounds__(256) void gemm_kernel(const float* __restrict__ W,
                                                   const float* __restrict__ bias,
                                                   const float* __restrict__ Wout,
                                                   const float* __restrict__ bout,
                                                   float* __restrict__ out) {
    const float* X = (const float*)g_a;
    __shared__ __align__(16) float smem_f[8192];
    int tid  = threadIdx.x;
    int lane = tid & 31;           // cols lane*4 .. +3
    int warp = tid >> 5;           // rows warp*8 .. +7
    int row0 = blockIdx.x * 64;

    float4 bv = *(const float4*)(bias + lane * 4);

    float acc[8][4];
    #pragma unroll
    for (int r = 0; r < 8; r++)
        #pragma unroll
        for (int c = 0; c < 4; c++) acc[r][c] = 0.f;

    for (int kc = 0; kc < DIN; kc += 32) {
        #pragma unroll
        for (int t = 0; t < 2; t++) {              // X tile 64x32, transposed
            int f = tid + t * 256;
            int r = f >> 3;
            int kq = (f & 7) << 2;
            float4 v = *(const float4*)(X + (row0 + r) * DIN + kc + kq);
            XS(kq+0, r) = v.x; XS(kq+1, r) = v.y;
            XS(kq+2, r) = v.z; XS(kq+3, r) = v.w;
        }
        #pragma unroll
        for (int t = 0; t < 4; t++) {              // W tile 32x128, direct
            int f = tid + t * 256;
            int k = f >> 5;
            int c = (f & 31) << 2;
            *(float4*)&WS(k, c) = *(const float4*)(W + (kc + k) * HH + c);
        }
        __syncthreads();
        #pragma unroll
        for (int k = 0; k < 32; k++) {
            float4 a0 = *(const float4*)&XS(k, warp*8);
            float4 a1 = *(const float4*)&XS(k, warp*8 + 4);
            float4 wv = *(const float4*)&WS(k, lane*4);
            float a[8] = {a0.x,a0.y,a0.z,a0.w,a1.x,a1.y,a1.z,a1.w};
            float bb[4] = {wv.x,wv.y,wv.z,wv.w};
            #pragma unroll
            for (int r = 0; r < 8; r++)
                #pragma unroll
                for (int c = 0; c < 4; c++)
                    acc[r][c] = fmaf(a[r], bb[c], acc[r][c]);
        }
        __syncthreads();
    }

    if (!FINAL) {
        #pragma unroll
        for (int r = 0; r < 8; r++) {
            float4 v;
            v.x = tanhf(acc[r][0] + bv.x);
            v.y = tanhf(acc[r][1] + bv.y);
            v.z = tanhf(acc[r][2] + bv.z);
            v.w = tanhf(acc[r][3] + bv.w);
            *(float4*)(g_h + (row0 + warp*8 + r) * HH + lane*4) = v;
        }
    } else {
        #pragma unroll
        for (int r = 0; r < 8; r++) {
            float4 v;
            v.x = tanhf(acc[r][0] + bv.x);
            v.y = tanhf(acc[r][1] + bv.y);
            v.z = tanhf(acc[r][2] + bv.z);
            v.w = tanhf(acc[r][3] + bv.w);
            *(float4*)&HS(warp*8 + r, lane*4) = v;
        }
        __syncthreads();
        float wreg[32];                           // Wout rows lane*4..+3 (8 outs each)
        #pragma unroll
        for (int i = 0; i < 8; i++)
            *(float4*)&wreg[i*4] = *(const float4*)(Wout + lane * 32 + i * 4);
        #pragma unroll
        for (int rr = 0; rr < 8; rr++) {
            int row = warp * 8 + rr;
            float4 hv = *(const float4*)&HS(row, lane*4);
            float hk[4] = {hv.x, hv.y, hv.z, hv.w};
            float a2[8];
            #pragma unroll
            for (int o = 0; o < 8; o++) a2[o] = 0.f;
            #pragma unroll
            for (int j = 0; j < 4; j++)
                #pragma unroll
                for (int o = 0; o < 8; o++)
                    a2[o] = fmaf(hk[j], wreg[j*8 + o], a2[o]);
            #pragma unroll
            for (int o = 0; o < 8; o++)
                #pragma unroll
                for (int s = 16; s >= 1; s >>= 1)
                    a2[o] += __shfl_xor_sync(0xffffffffu, a2[o], s);
            if (lane == 0) {
                int m = row0 + row;
                float mf = g_maskf[m];
                #pragma unroll
                for (int o = 0; o < 8; o++)
                    out[m * OUTD + o] = (a2[o] + bout[o]) * mf;
            }
        }
    }
}

// ---------------- launch ------------------------------------------------------
extern "C" void kernel_launch(void* const* d_in, const int* in_sizes, int n_in,
                              void* d_out, int out_size) {
    const float* obs  = (const float*)d_in[0];
    const float* W1   = (const float*)d_in[1];
    const float* b1   = (const float*)d_in[2];
    const float* W2   = (const float*)d_in[3];
    const float* b2   = (const float*)d_in[4];
    const float* Wout = (const float*)d_in[5];
    const float* bout = (const float*)d_in[6];
    float* out = (float*)d_out;

    prep_kernel   <<<NODES/256, 256>>>(obs);
    topk_kernel   <<<dim3(NN/8, BB), 256>>>();      // kNN + fused scatter
    listify_kernel<<<NODES/8, 256>>>();

    pregather_kernel<DD, true> <<<NODES/8, 128>>>(obs);
    gemm_kernel<DD, false><<<NODES/64, 256>>>(W1, b1, 0, 0, 0);
    pregather_kernel<HH, false><<<NODES/4, 128>>>(obs);
    gemm_kernel<HH, true><<<NODES/64, 256>>>(W2, b2, Wout, bout, out);
}